// round 3
// baseline (speedup 1.0000x reference)
#include <cuda_runtime.h>
#include <cstdint>
#include <math.h>

// ---------------------------------------------------------------------------
// Scratch buffers (no cudaMalloc allowed): ~47 MB of __device__ globals.
// Layout of sequence buffers: (T*B, C, H, W) with batch index = t*8 + b.
// ---------------------------------------------------------------------------
__device__ float g_feat1[80u * 16 * 64 * 64];   //  5.24M
__device__ float g_outs1[80u * 64 * 64 * 64];   // 20.97M
__device__ float g_feat2[80u * 64 * 32 * 32];   //  5.24M
__device__ float g_outs2[80u * 96 * 32 * 32];   //  7.86M
__device__ float g_feat3[80u * 96 * 16 * 16];   //  1.97M
__device__ float g_outs3[80u * 96 * 16 * 16];   //  1.97M
__device__ float g_rh   [8u * 64 * 64 * 64];    //  2.10M (max over stages)
__device__ float g_zb   [8u * 64 * 64 * 64];    //  2.10M

// ---------------------------------------------------------------------------
// Generic 3x3 conv (pad 1, stride S in {1,2}) with fused epilogues.
//   MODE 0: leaky_relu(v, 0.2)                  -> out0   (stem convs)
//   MODE 1: gates: s=sigmoid(v); oc<hid -> out0[rh]=s*h ; oc>=hid -> out1[z]=s
//   MODE 2: cand:  c=tanh(v); out0[h_new] = z*h + (1-z)*c
// Input is the implicit concat [in0 (C0 ch) | in1 (C1 ch)]; in1 may be null
// (treated as zeros, i.e. t==0 hidden state).
//
// Tiling: block covers TLW output cols x full OH rows x IMGS batch images.
// Each thread: PIX=4 consecutive output rows x OUTG=4 output channels.
// Per input channel: 3x(PIX*S+...) register neighborhood + 9 weights/oc.
// ---------------------------------------------------------------------------
template<int OH, int OW, int IH, int IW, int S, int TLW,
         int PIX, int IMGS, int OUTG, int CHUNK, int MODE>
__global__ void __launch_bounds__(TLW*(OH/PIX)*IMGS)
conv3x3_k(const float* __restrict__ in0, int C0,
          const float* __restrict__ in1, int C1,
          const float* __restrict__ wgt, const float* __restrict__ bias,
          const float* __restrict__ zb,  const float* __restrict__ hprev,
          float* __restrict__ out0, float* __restrict__ out1,
          int Cout, int xpose)
{
    constexpr int NT  = TLW * (OH / PIX) * IMGS;   // always 256 in our configs
    constexpr int ITH = S * OH + 2;                // input tile rows (+halo)
    constexpr int ITW = S * TLW + 2;               // input tile cols (+halo)
    constexpr int IVR = S * (PIX - 1) + 3;         // register rows per thread

    __shared__ float s_in[IMGS][CHUNK][ITH][ITW];
    __shared__ float s_w [OUTG][CHUNK][9];

    const int tid = threadIdx.x;
    const int tx  = tid % TLW;
    const int ty  = (tid / TLW) % (OH / PIX);
    const int im  = tid / (TLW * (OH / PIX));
    const int y0  = ty * PIX;
    const int x0  = blockIdx.x * TLW;
    const int oc0 = blockIdx.z * OUTG;
    const int Ctot = C0 + C1;
    const int Ceff = in1 ? Ctot : C0;

    float acc[PIX][OUTG];
#pragma unroll
    for (int p = 0; p < PIX; p++)
#pragma unroll
        for (int og = 0; og < OUTG; og++) acc[p][og] = 0.f;

    for (int cc0 = 0; cc0 < Ceff; cc0 += CHUNK) {
        __syncthreads();
        // ---- weights slice: OUTG x CHUNK x 9 ----
        for (int i = tid; i < OUTG * CHUNK * 9; i += NT) {
            int k = i % 9; int t2 = i / 9;
            int c = t2 % CHUNK; int og = t2 / CHUNK;
            s_w[og][c][k] =
                wgt[((size_t)(oc0 + og) * Ctot + cc0 + c) * 9 + k];
        }
        // ---- input tile (with zero-padded halo) ----
        constexpr int TOT = IMGS * CHUNK * ITH * ITW;
        for (int i = tid; i < TOT; i += NT) {
            int xx = i % ITW; int t2 = i / ITW;
            int yy = t2 % ITH; t2 /= ITH;
            int c  = t2 % CHUNK; int imm = t2 / CHUNK;
            int gy = yy - 1;
            int gx = S * x0 - 1 + xx;
            int ci = cc0 + c;
            float v = 0.f;
            if ((unsigned)gy < (unsigned)IH && (unsigned)gx < (unsigned)IW) {
                int bb = blockIdx.y * IMGS + imm;
                const float* p; int ch, Cc;
                if (ci < C0) {
                    p = in0; ch = ci; Cc = C0;
                    if (xpose) bb = (bb & 7) * 10 + (bb >> 3);  // (t,b)->(b,t)
                } else {
                    p = in1; ch = ci - C0; Cc = C1;
                }
                v = p[(((size_t)bb * Cc + ch) * IH + gy) * IW + gx];
            }
            s_in[imm][c][yy][xx] = v;
        }
        __syncthreads();

        // ---- compute ----
#pragma unroll
        for (int c = 0; c < CHUNK; c++) {
            float iv[IVR][3];
#pragma unroll
            for (int r = 0; r < IVR; r++)
#pragma unroll
                for (int q = 0; q < 3; q++)
                    iv[r][q] = s_in[im][c][S * y0 + r][S * tx + q];
#pragma unroll
            for (int og = 0; og < OUTG; og++) {
                float wv[9];
#pragma unroll
                for (int k = 0; k < 9; k++) wv[k] = s_w[og][c][k];
#pragma unroll
                for (int p = 0; p < PIX; p++)
#pragma unroll
                    for (int ky = 0; ky < 3; ky++)
#pragma unroll
                        for (int kx = 0; kx < 3; kx++)
                            acc[p][og] = fmaf(iv[S * p + ky][kx],
                                              wv[ky * 3 + kx], acc[p][og]);
            }
        }
    }

    // ---- epilogue ----
    const int bb = blockIdx.y * IMGS + im;
    const int x  = x0 + tx;
#pragma unroll
    for (int og = 0; og < OUTG; og++) {
        const int oc = oc0 + og;
        const float bv = bias[oc];
#pragma unroll
        for (int p = 0; p < PIX; p++) {
            const int y = y0 + p;
            float v = acc[p][og] + bv;
            const size_t sp = (size_t)y * OW + x;
            if (MODE == 0) {
                out0[((size_t)bb * Cout + oc) * (OH * OW) + sp] =
                    v > 0.f ? v : 0.2f * v;
            } else if (MODE == 1) {
                const int hid = Cout >> 1;
                const float s = 1.f / (1.f + __expf(-v));
                if (oc < hid) {
                    const size_t idx = ((size_t)bb * hid + oc) * (OH * OW) + sp;
                    const float hv = hprev ? hprev[idx] : 0.f;
                    out0[idx] = s * hv;                       // r * h
                } else {
                    out1[((size_t)bb * hid + (oc - hid)) * (OH * OW) + sp] = s; // z
                }
            } else {
                const size_t idx = ((size_t)bb * Cout + oc) * (OH * OW) + sp;
                const float z  = zb[idx];
                const float hv = hprev ? hprev[idx] : 0.f;
                const float cd = tanhf(v);
                out0[idx] = z * hv + (1.f - z) * cd;          // new hidden
            }
        }
    }
}

// ---------------------------------------------------------------------------
extern "C" void kernel_launch(void* const* d_in, const int* in_sizes, int n_in,
                              void* d_out, int out_size)
{
    (void)in_sizes; (void)n_in; (void)out_size;
    const float* x   = (const float*)d_in[0];
    const float* W1  = (const float*)d_in[1];   const float* b1  = (const float*)d_in[2];
    const float* Wg1 = (const float*)d_in[3];   const float* bg1 = (const float*)d_in[4];
    const float* Wc1 = (const float*)d_in[5];   const float* bc1 = (const float*)d_in[6];
    const float* W2  = (const float*)d_in[7];   const float* b2  = (const float*)d_in[8];
    const float* Wg2 = (const float*)d_in[9];   const float* bg2 = (const float*)d_in[10];
    const float* Wc2 = (const float*)d_in[11];  const float* bc2 = (const float*)d_in[12];
    const float* W3  = (const float*)d_in[13];  const float* b3  = (const float*)d_in[14];
    const float* Wg3 = (const float*)d_in[15];  const float* bg3 = (const float*)d_in[16];
    const float* Wc3 = (const float*)d_in[17];  const float* bc3 = (const float*)d_in[18];

    float *feat1, *outs1, *feat2, *outs2, *feat3, *outs3, *rh, *zb;
    cudaGetSymbolAddress((void**)&feat1, g_feat1);
    cudaGetSymbolAddress((void**)&outs1, g_outs1);
    cudaGetSymbolAddress((void**)&feat2, g_feat2);
    cudaGetSymbolAddress((void**)&outs2, g_outs2);
    cudaGetSymbolAddress((void**)&feat3, g_feat3);
    cudaGetSymbolAddress((void**)&outs3, g_outs3);
    cudaGetSymbolAddress((void**)&rh,    g_rh);
    cudaGetSymbolAddress((void**)&zb,    g_zb);

    float* out = (float*)d_out;

    // ======================= Stage 1: 128 -> 64, hid 64 ====================
    // stem conv 1->16, stride 2, leaky_relu, batch = T*B = 80 (x is (B,T,...): xpose)
    conv3x3_k<64,64,128,128,2,16,4,1,4,1,0><<<dim3(4,80,4),256>>>(
        x,1, nullptr,0, W1,b1, nullptr,nullptr, feat1,nullptr, 16, 1);

    for (int t = 0; t < 10; t++) {
        const float* ft = feat1 + (size_t)t * 8 * 16 * 64 * 64;
        const float* hp = t ? outs1 + (size_t)(t-1) * 8 * 64 * 64 * 64 : nullptr;
        float*       ho = outs1 + (size_t)t * 8 * 64 * 64 * 64;
        // gates: conv([x,h], 80->128), sigmoid; writes rh = r*h and z
        conv3x3_k<64,64,64,64,1,16,4,1,4,4,1><<<dim3(4,8,32),256>>>(
            ft,16, hp,64, Wg1,bg1, nullptr,hp, rh,zb, 128, 0);
        // cand: conv([x,r*h], 80->64), tanh; h_new = z*h + (1-z)*cand
        conv3x3_k<64,64,64,64,1,16,4,1,4,4,2><<<dim3(4,8,16),256>>>(
            ft,16, rh,64, Wc1,bc1, zb,hp, ho,nullptr, 64, 0);
    }
    cudaMemcpyAsync(out, outs1 + (size_t)9 * 8 * 64 * 64 * 64,
                    (size_t)8 * 64 * 64 * 64 * sizeof(float),
                    cudaMemcpyDeviceToDevice);

    // ======================= Stage 2: 64 -> 32, hid 96 =====================
    conv3x3_k<32,32,64,64,2,32,4,1,4,1,0><<<dim3(1,80,16),256>>>(
        outs1,64, nullptr,0, W2,b2, nullptr,nullptr, feat2,nullptr, 64, 0);

    for (int t = 0; t < 10; t++) {
        const float* ft = feat2 + (size_t)t * 8 * 64 * 32 * 32;
        const float* hp = t ? outs2 + (size_t)(t-1) * 8 * 96 * 32 * 32 : nullptr;
        float*       ho = outs2 + (size_t)t * 8 * 96 * 32 * 32;
        conv3x3_k<32,32,32,32,1,32,4,1,4,4,1><<<dim3(1,8,48),256>>>(
            ft,64, hp,96, Wg2,bg2, nullptr,hp, rh,zb, 192, 0);
        conv3x3_k<32,32,32,32,1,32,4,1,4,4,2><<<dim3(1,8,24),256>>>(
            ft,64, rh,96, Wc2,bc2, zb,hp, ho,nullptr, 96, 0);
    }
    cudaMemcpyAsync(out + 2097152, outs2 + (size_t)9 * 8 * 96 * 32 * 32,
                    (size_t)8 * 96 * 32 * 32 * sizeof(float),
                    cudaMemcpyDeviceToDevice);

    // ======================= Stage 3: 32 -> 16, hid 96 =====================
    conv3x3_k<16,16,32,32,2,16,4,4,4,1,0><<<dim3(1,20,24),256>>>(
        outs2,96, nullptr,0, W3,b3, nullptr,nullptr, feat3,nullptr, 96, 0);

    for (int t = 0; t < 10; t++) {
        const float* ft = feat3 + (size_t)t * 8 * 96 * 16 * 16;
        const float* hp = t ? outs3 + (size_t)(t-1) * 8 * 96 * 16 * 16 : nullptr;
        float*       ho = outs3 + (size_t)t * 8 * 96 * 16 * 16;
        conv3x3_k<16,16,16,16,1,16,4,4,4,4,1><<<dim3(1,2,48),256>>>(
            ft,96, hp,96, Wg3,bg3, nullptr,hp, rh,zb, 192, 0);
        conv3x3_k<16,16,16,16,1,16,4,4,4,4,2><<<dim3(1,2,24),256>>>(
            ft,96, rh,96, Wc3,bc3, zb,hp, ho,nullptr, 96, 0);
    }
    cudaMemcpyAsync(out + 2883584, outs3 + (size_t)9 * 8 * 96 * 16 * 16,
                    (size_t)8 * 96 * 16 * 16 * sizeof(float),
                    cudaMemcpyDeviceToDevice);
}

// round 9
// speedup vs baseline: 2.1996x; 2.1996x over previous
#include <cuda_runtime.h>
#include <cstdint>
#include <math.h>

// ---------------------------------------------------------------------------
// Scratch buffers (no cudaMalloc allowed). (T*B, C, H, W), batch = t*8 + b.
// ---------------------------------------------------------------------------
__device__ __align__(16) float g_feat1[80u * 16 * 64 * 64];
__device__ __align__(16) float g_outs1[80u * 64 * 64 * 64];
__device__ __align__(16) float g_feat2[80u * 64 * 32 * 32];
__device__ __align__(16) float g_outs2[80u * 96 * 32 * 32];
__device__ __align__(16) float g_feat3[80u * 96 * 16 * 16];
__device__ __align__(16) float g_outs3[80u * 96 * 16 * 16];
__device__ __align__(16) float g_rh   [8u * 64 * 64 * 64];
__device__ __align__(16) float g_zb   [8u * 64 * 64 * 64];

// Row stride (floats): multiple of 4 (16B STS.128), prefer dy*RS % 32 == 16
// so adjacent-ty lanes hit disjoint bank halves.
__host__ __device__ constexpr int pick_rs(int base, int dy) {
    int r = (base + 3) & ~3;
    for (int i = 0; i < 8; i++) { if ((dy * r) % 32 == 16) return r; r += 4; }
    return (base + 3) & ~3;
}

// ---------------------------------------------------------------------------
// 3x3 conv (pad 1, stride S in {1,2}) with fused epilogues.
//   MODE 0: leaky_relu(v,0.2) -> out0
//   MODE 1: s=sigmoid(v); oc<hid -> out0[rh]=s*h ; oc>=hid -> out1[z]=s
//   MODE 2: c=tanh(v); out0 = z*h + (1-z)*c
// Implicit concat input [in0 (C0) | in1 (C1)]; in1 null => zeros (t==0).
// Block: TLW output cols x OH rows x IMGS images; thread: PIX rows x OUTG ocs.
// ---------------------------------------------------------------------------
template<int OH, int OW, int IH, int IW, int S, int TLW,
         int PIX, int IMGS, int OUTG, int CHUNK, int MODE>
__global__ void __launch_bounds__(TLW*(OH/PIX)*IMGS)
conv3x3_k(const float* __restrict__ in0, int C0,
          const float* __restrict__ in1, int C1,
          const float* __restrict__ wgt, const float* __restrict__ bias,
          const float* __restrict__ zb,  const float* __restrict__ hprev,
          float* __restrict__ out0, float* __restrict__ out1,
          int Cout, int xpose)
{
    constexpr int NT    = TLW * (OH / PIX) * IMGS;      // 256 in all configs
    constexpr int ITH   = S * OH + 2;                   // input tile rows
    constexpr int W_INT = S * TLW;                      // interior cols
    constexpr int IVR   = S * (PIX - 1) + 3;            // reg rows / thread
    constexpr int DY    = S * PIX;                      // row delta per ty
    constexpr int RS    = pick_rs(W_INT + 5, DY);       // smem row stride
    constexpr int XOFF  = 4;                            // interior start idx
    constexpr int SEGW  = (W_INT <= 16) ? W_INT : 16;   // floats per segment
    constexpr int NSEG  = W_INT / SEGW;
    constexpr int R     = IMGS * CHUNK * ITH;           // tile rows total
    constexpr int U     = R * NSEG;                     // load units

    __shared__ __align__(16) float s_in[IMGS * CHUNK * ITH * RS];
    __shared__ float s_w[OUTG][CHUNK][9];

    const int tid = threadIdx.x;
    const int tx  = tid % TLW;
    const int ty  = (tid / TLW) % (OH / PIX);
    const int im  = tid / (TLW * (OH / PIX));
    const int y0  = ty * PIX;
    const int x0  = blockIdx.x * TLW;
    const int oc0 = blockIdx.z * OUTG;
    const int Ctot = C0 + C1;
    const int Ceff = in1 ? Ctot : C0;

    float acc[PIX][OUTG];
#pragma unroll
    for (int p = 0; p < PIX; p++)
#pragma unroll
        for (int og = 0; og < OUTG; og++) acc[p][og] = 0.f;

    for (int cc0 = 0; cc0 < Ceff; cc0 += CHUNK) {
        __syncthreads();
        // ---- weights: OUTG x CHUNK x 9 ----
        for (int i = tid; i < OUTG * CHUNK * 9; i += NT) {
            int k = i % 9; int t2 = i / 9;
            int c = t2 % CHUNK; int og = t2 / CHUNK;
            s_w[og][c][k] = wgt[((size_t)(oc0 + og) * Ctot + cc0 + c) * 9 + k];
        }
        // ---- interior: one addr computation per SEGW-float segment ----
        for (int u = tid; u < U; u += NT) {
            const int row = u / NSEG;
            const int seg = u - row * NSEG;
            const int yy  = row % ITH;
            const int t2  = row / ITH;
            const int c   = t2 % CHUNK;
            const int imm = t2 / CHUNK;
            const int gy  = yy - 1;
            const int ci  = cc0 + c;
            int bb = blockIdx.y * IMGS + imm;
            const float* p; int ch, Cc;
            if (ci < C0) {
                p = in0; ch = ci; Cc = C0;
                if (xpose) bb = (bb & 7) * 10 + (bb >> 3);
            } else { p = in1; ch = ci - C0; Cc = C1; }
            const bool rv = (unsigned)gy < (unsigned)IH;
            const float4* gp = (const float4*)
                (p + (((size_t)bb * Cc + ch) * IH + gy) * IW + S * x0 + seg * SEGW);
            float* sp = &s_in[((imm * CHUNK + c) * ITH + yy) * RS + XOFF + seg * SEGW];
#pragma unroll
            for (int k = 0; k < SEGW / 4; k++) {
                float4 v = rv ? gp[k] : make_float4(0.f, 0.f, 0.f, 0.f);
                *(float4*)(sp + 4 * k) = v;
            }
        }
        // ---- halo columns (2 per row) ----
        for (int row = tid; row < R; row += NT) {
            const int yy  = row % ITH;
            const int t2  = row / ITH;
            const int c   = t2 % CHUNK;
            const int imm = t2 / CHUNK;
            const int gy  = yy - 1;
            const int ci  = cc0 + c;
            int bb = blockIdx.y * IMGS + imm;
            const float* p; int ch, Cc;
            if (ci < C0) {
                p = in0; ch = ci; Cc = C0;
                if (xpose) bb = (bb & 7) * 10 + (bb >> 3);
            } else { p = in1; ch = ci - C0; Cc = C1; }
            const bool rv = (unsigned)gy < (unsigned)IH;
            const float* rb = p + (((size_t)bb * Cc + ch) * IH + gy) * IW;
            const int gxl = S * x0 - 1, gxr = S * x0 + W_INT;
            float* sr = &s_in[((imm * CHUNK + c) * ITH + yy) * RS];
            sr[XOFF - 1]     = (rv && gxl >= 0) ? rb[gxl] : 0.f;
            sr[XOFF + W_INT] = (rv && gxr < IW) ? rb[gxr] : 0.f;
        }
        __syncthreads();

        // ---- compute ----
        const float* sbase = &s_in[(im * CHUNK) * ITH * RS];
#pragma unroll
        for (int c = 0; c < CHUNK; c++) {
            float iv[IVR][3];
#pragma unroll
            for (int r = 0; r < IVR; r++)
#pragma unroll
                for (int q = 0; q < 3; q++)
                    iv[r][q] = sbase[(c * ITH + S * y0 + r) * RS
                                     + (XOFF - 1) + S * tx + q];
#pragma unroll
            for (int og = 0; og < OUTG; og++) {
                float wv[9];
#pragma unroll
                for (int k = 0; k < 9; k++) wv[k] = s_w[og][c][k];
#pragma unroll
                for (int p = 0; p < PIX; p++)
#pragma unroll
                    for (int ky = 0; ky < 3; ky++)
#pragma unroll
                        for (int kx = 0; kx < 3; kx++)
                            acc[p][og] = fmaf(iv[S * p + ky][kx],
                                              wv[ky * 3 + kx], acc[p][og]);
            }
        }
    }

    // ---- epilogue ----
    const int bb = blockIdx.y * IMGS + im;
    const int x  = x0 + tx;
#pragma unroll
    for (int og = 0; og < OUTG; og++) {
        const int oc = oc0 + og;
        const float bv = bias[oc];
#pragma unroll
        for (int p = 0; p < PIX; p++) {
            const int y = y0 + p;
            float v = acc[p][og] + bv;
            const size_t sp = (size_t)y * OW + x;
            if (MODE == 0) {
                out0[((size_t)bb * Cout + oc) * (OH * OW) + sp] =
                    v > 0.f ? v : 0.2f * v;
            } else if (MODE == 1) {
                const int hid = Cout >> 1;
                const float s = 1.f / (1.f + __expf(-v));
                if (oc < hid) {
                    const size_t idx = ((size_t)bb * hid + oc) * (OH * OW) + sp;
                    const float hv = hprev ? hprev[idx] : 0.f;
                    out0[idx] = s * hv;                       // r*h
                } else {
                    out1[((size_t)bb * hid + (oc - hid)) * (OH * OW) + sp] = s; // z
                }
            } else {
                const size_t idx = ((size_t)bb * Cout + oc) * (OH * OW) + sp;
                const float z  = zb[idx];
                const float hv = hprev ? hprev[idx] : 0.f;
                const float cd = tanhf(v);
                out0[idx] = z * hv + (1.f - z) * cd;
            }
        }
    }
}

// ---------------------------------------------------------------------------
extern "C" void kernel_launch(void* const* d_in, const int* in_sizes, int n_in,
                              void* d_out, int out_size)
{
    (void)in_sizes; (void)n_in; (void)out_size;
    const float* x   = (const float*)d_in[0];
    const float* W1  = (const float*)d_in[1];   const float* b1  = (const float*)d_in[2];
    const float* Wg1 = (const float*)d_in[3];   const float* bg1 = (const float*)d_in[4];
    const float* Wc1 = (const float*)d_in[5];   const float* bc1 = (const float*)d_in[6];
    const float* W2  = (const float*)d_in[7];   const float* b2  = (const float*)d_in[8];
    const float* Wg2 = (const float*)d_in[9];   const float* bg2 = (const float*)d_in[10];
    const float* Wc2 = (const float*)d_in[11];  const float* bc2 = (const float*)d_in[12];
    const float* W3  = (const float*)d_in[13];  const float* b3  = (const float*)d_in[14];
    const float* Wg3 = (const float*)d_in[15];  const float* bg3 = (const float*)d_in[16];
    const float* Wc3 = (const float*)d_in[17];  const float* bc3 = (const float*)d_in[18];

    float *feat1, *outs1, *feat2, *outs2, *feat3, *outs3, *rh, *zb;
    cudaGetSymbolAddress((void**)&feat1, g_feat1);
    cudaGetSymbolAddress((void**)&outs1, g_outs1);
    cudaGetSymbolAddress((void**)&feat2, g_feat2);
    cudaGetSymbolAddress((void**)&outs2, g_outs2);
    cudaGetSymbolAddress((void**)&feat3, g_feat3);
    cudaGetSymbolAddress((void**)&outs3, g_outs3);
    cudaGetSymbolAddress((void**)&rh,    g_rh);
    cudaGetSymbolAddress((void**)&zb,    g_zb);

    float* out = (float*)d_out;

    // ======================= Stage 1: 128 -> 64, hid 64 ====================
    conv3x3_k<64,64,128,128,2,16,4,1,4,1,0><<<dim3(4,80,4),256>>>(
        x,1, nullptr,0, W1,b1, nullptr,nullptr, feat1,nullptr, 16, 1);

    for (int t = 0; t < 10; t++) {
        const float* ft = feat1 + (size_t)t * 8 * 16 * 64 * 64;
        const float* hp = t ? outs1 + (size_t)(t-1) * 8 * 64 * 64 * 64 : nullptr;
        float*       ho = outs1 + (size_t)t * 8 * 64 * 64 * 64;
        conv3x3_k<64,64,64,64,1,16,4,1,4,4,1><<<dim3(4,8,32),256>>>(
            ft,16, hp,64, Wg1,bg1, nullptr,hp, rh,zb, 128, 0);
        conv3x3_k<64,64,64,64,1,16,4,1,4,4,2><<<dim3(4,8,16),256>>>(
            ft,16, rh,64, Wc1,bc1, zb,hp, ho,nullptr, 64, 0);
    }
    cudaMemcpyAsync(out, outs1 + (size_t)9 * 8 * 64 * 64 * 64,
                    (size_t)8 * 64 * 64 * 64 * sizeof(float),
                    cudaMemcpyDeviceToDevice);

    // ======================= Stage 2: 64 -> 32, hid 96 =====================
    conv3x3_k<32,32,64,64,2,32,4,1,4,1,0><<<dim3(1,80,16),256>>>(
        outs1,64, nullptr,0, W2,b2, nullptr,nullptr, feat2,nullptr, 64, 0);

    for (int t = 0; t < 10; t++) {
        const float* ft = feat2 + (size_t)t * 8 * 64 * 32 * 32;
        const float* hp = t ? outs2 + (size_t)(t-1) * 8 * 96 * 32 * 32 : nullptr;
        float*       ho = outs2 + (size_t)t * 8 * 96 * 32 * 32;
        conv3x3_k<32,32,32,32,1,32,4,1,4,4,1><<<dim3(1,8,48),256>>>(
            ft,64, hp,96, Wg2,bg2, nullptr,hp, rh,zb, 192, 0);
        conv3x3_k<32,32,32,32,1,32,4,1,4,4,2><<<dim3(1,8,24),256>>>(
            ft,64, rh,96, Wc2,bc2, zb,hp, ho,nullptr, 96, 0);
    }
    cudaMemcpyAsync(out + 2097152, outs2 + (size_t)9 * 8 * 96 * 32 * 32,
                    (size_t)8 * 96 * 32 * 32 * sizeof(float),
                    cudaMemcpyDeviceToDevice);

    // ======================= Stage 3: 32 -> 16, hid 96 =====================
    conv3x3_k<16,16,32,32,2,16,4,4,4,1,0><<<dim3(1,20,24),256>>>(
        outs2,96, nullptr,0, W3,b3, nullptr,nullptr, feat3,nullptr, 96, 0);

    for (int t = 0; t < 10; t++) {
        const float* ft = feat3 + (size_t)t * 8 * 96 * 16 * 16;
        const float* hp = t ? outs3 + (size_t)(t-1) * 8 * 96 * 16 * 16 : nullptr;
        float*       ho = outs3 + (size_t)t * 8 * 96 * 16 * 16;
        conv3x3_k<16,16,16,16,1,16,4,4,4,4,1><<<dim3(1,2,48),256>>>(
            ft,96, hp,96, Wg3,bg3, nullptr,hp, rh,zb, 192, 0);
        conv3x3_k<16,16,16,16,1,16,4,4,4,4,2><<<dim3(1,2,24),256>>>(
            ft,96, rh,96, Wc3,bc3, zb,hp, ho,nullptr, 96, 0);
    }
    cudaMemcpyAsync(out + 2883584, outs3 + (size_t)9 * 8 * 96 * 16 * 16,
                    (size_t)8 * 96 * 16 * 16 * sizeof(float),
                    cudaMemcpyDeviceToDevice);
}

// round 12
// speedup vs baseline: 2.4693x; 1.1226x over previous
#include <cuda_runtime.h>
#include <cstdint>
#include <math.h>

// ---------------------------------------------------------------------------
// Scratch buffers (no cudaMalloc allowed). (T*B, C, H, W), batch = t*8 + b.
// ---------------------------------------------------------------------------
__device__ __align__(16) float g_feat1[80u * 16 * 64 * 64];
__device__ __align__(16) float g_outs1[80u * 64 * 64 * 64];
__device__ __align__(16) float g_feat2[80u * 64 * 32 * 32];
__device__ __align__(16) float g_outs2[80u * 96 * 32 * 32];
__device__ __align__(16) float g_feat3[80u * 96 * 16 * 16];
__device__ __align__(16) float g_outs3[80u * 96 * 16 * 16];
__device__ __align__(16) float g_rh   [8u * 64 * 64 * 64];
__device__ __align__(16) float g_zb   [8u * 64 * 64 * 64];
// duplicated (w,w) weights for the 6 GRU convs, expanded at launch
__device__ __align__(16) float2 g_wdup[1050624];

__host__ __device__ constexpr int pick_rs(int base, int dy) {
    int r = (base + 3) & ~3;
    for (int i = 0; i < 8; i++) { if ((dy * r) % 32 == 16) return r; r += 4; }
    return (base + 3) & ~3;
}

// ---------------- cp.async / f32x2 helpers ---------------------------------
__device__ __forceinline__ void cp16(uint32_t d, const void* s, int sz) {
    asm volatile("cp.async.ca.shared.global [%0], [%1], 16, %2;"
                 :: "r"(d), "l"(s), "r"(sz));
}
__device__ __forceinline__ void cp8(uint32_t d, const void* s) {
    asm volatile("cp.async.ca.shared.global [%0], [%1], 8;"
                 :: "r"(d), "l"(s));
}
__device__ __forceinline__ void cp4(uint32_t d, const void* s, int sz) {
    asm volatile("cp.async.ca.shared.global [%0], [%1], 4, %2;"
                 :: "r"(d), "l"(s), "r"(sz));
}
#define CP_COMMIT() asm volatile("cp.async.commit_group;" ::: "memory")
template<int N> __device__ __forceinline__ void cp_wait() {
    asm volatile("cp.async.wait_group %0;" :: "n"(N) : "memory");
}
__device__ __forceinline__ unsigned long long packf2(float lo, float hi) {
    unsigned long long r;
    asm("mov.b64 %0, {%1, %2};" : "=l"(r) : "f"(lo), "f"(hi));
    return r;
}
__device__ __forceinline__ float2 unpk(unsigned long long v) {
    float2 r;
    asm("mov.b64 {%0, %1}, %2;" : "=f"(r.x), "=f"(r.y) : "l"(v));
    return r;
}
__device__ __forceinline__ void ffma2(unsigned long long& d,
                                      unsigned long long a, unsigned long long b) {
    asm("fma.rn.f32x2 %0, %1, %2, %0;" : "+l"(d) : "l"(a), "l"(b));
}

// Weight duplication: w[i] -> (w[i], w[i])
__global__ void dup_w(const float* __restrict__ w, float2* __restrict__ o, int n) {
    int i = blockIdx.x * 256 + threadIdx.x;
    if (i < n) { float v = w[i]; o[i] = make_float2(v, v); }
}

// ---------------------------------------------------------------------------
// Stem template (stride-2 conv, leaky_relu) — proven R9 path, unchanged.
// ---------------------------------------------------------------------------
template<int OH, int OW, int IH, int IW, int S, int TLW,
         int PIX, int IMGS, int OUTG, int CHUNK, int MODE>
__global__ void __launch_bounds__(TLW*(OH/PIX)*IMGS)
conv3x3_k(const float* __restrict__ in0, int C0,
          const float* __restrict__ in1, int C1,
          const float* __restrict__ wgt, const float* __restrict__ bias,
          const float* __restrict__ zb,  const float* __restrict__ hprev,
          float* __restrict__ out0, float* __restrict__ out1,
          int Cout, int xpose)
{
    constexpr int NT    = TLW * (OH / PIX) * IMGS;
    constexpr int ITH   = S * OH + 2;
    constexpr int W_INT = S * TLW;
    constexpr int IVR   = S * (PIX - 1) + 3;
    constexpr int DY    = S * PIX;
    constexpr int RS    = pick_rs(W_INT + 5, DY);
    constexpr int XOFF  = 4;
    constexpr int SEGW  = (W_INT <= 16) ? W_INT : 16;
    constexpr int NSEG  = W_INT / SEGW;
    constexpr int R     = IMGS * CHUNK * ITH;
    constexpr int U     = R * NSEG;

    __shared__ __align__(16) float s_in[IMGS * CHUNK * ITH * RS];
    __shared__ float s_w[OUTG][CHUNK][9];

    const int tid = threadIdx.x;
    const int tx  = tid % TLW;
    const int ty  = (tid / TLW) % (OH / PIX);
    const int im  = tid / (TLW * (OH / PIX));
    const int y0  = ty * PIX;
    const int x0  = blockIdx.x * TLW;
    const int oc0 = blockIdx.z * OUTG;
    const int Ctot = C0 + C1;
    const int Ceff = in1 ? Ctot : C0;

    float acc[PIX][OUTG];
#pragma unroll
    for (int p = 0; p < PIX; p++)
#pragma unroll
        for (int og = 0; og < OUTG; og++) acc[p][og] = 0.f;

    for (int cc0 = 0; cc0 < Ceff; cc0 += CHUNK) {
        __syncthreads();
        for (int i = tid; i < OUTG * CHUNK * 9; i += NT) {
            int k = i % 9; int t2 = i / 9;
            int c = t2 % CHUNK; int og = t2 / CHUNK;
            s_w[og][c][k] = wgt[((size_t)(oc0 + og) * Ctot + cc0 + c) * 9 + k];
        }
        for (int u = tid; u < U; u += NT) {
            const int row = u / NSEG;
            const int seg = u - row * NSEG;
            const int yy  = row % ITH;
            const int t2  = row / ITH;
            const int c   = t2 % CHUNK;
            const int imm = t2 / CHUNK;
            const int gy  = yy - 1;
            const int ci  = cc0 + c;
            int bb = blockIdx.y * IMGS + imm;
            const float* p; int ch, Cc;
            if (ci < C0) {
                p = in0; ch = ci; Cc = C0;
                if (xpose) bb = (bb & 7) * 10 + (bb >> 3);
            } else { p = in1; ch = ci - C0; Cc = C1; }
            const bool rv = (unsigned)gy < (unsigned)IH;
            const float4* gp = (const float4*)
                (p + (((size_t)bb * Cc + ch) * IH + gy) * IW + S * x0 + seg * SEGW);
            float* sp = &s_in[((imm * CHUNK + c) * ITH + yy) * RS + XOFF + seg * SEGW];
#pragma unroll
            for (int k = 0; k < SEGW / 4; k++) {
                float4 v = rv ? gp[k] : make_float4(0.f, 0.f, 0.f, 0.f);
                *(float4*)(sp + 4 * k) = v;
            }
        }
        for (int row = tid; row < R; row += NT) {
            const int yy  = row % ITH;
            const int t2  = row / ITH;
            const int c   = t2 % CHUNK;
            const int imm = t2 / CHUNK;
            const int gy  = yy - 1;
            const int ci  = cc0 + c;
            int bb = blockIdx.y * IMGS + imm;
            const float* p; int ch, Cc;
            if (ci < C0) {
                p = in0; ch = ci; Cc = C0;
                if (xpose) bb = (bb & 7) * 10 + (bb >> 3);
            } else { p = in1; ch = ci - C0; Cc = C1; }
            const bool rv = (unsigned)gy < (unsigned)IH;
            const float* rb = p + (((size_t)bb * Cc + ch) * IH + gy) * IW;
            const int gxl = S * x0 - 1, gxr = S * x0 + W_INT;
            float* sr = &s_in[((imm * CHUNK + c) * ITH + yy) * RS];
            sr[XOFF - 1]     = (rv && gxl >= 0) ? rb[gxl] : 0.f;
            sr[XOFF + W_INT] = (rv && gxr < IW) ? rb[gxr] : 0.f;
        }
        __syncthreads();

        const float* sbase = &s_in[(im * CHUNK) * ITH * RS];
#pragma unroll
        for (int c = 0; c < CHUNK; c++) {
            float iv[IVR][3];
#pragma unroll
            for (int r = 0; r < IVR; r++)
#pragma unroll
                for (int q = 0; q < 3; q++)
                    iv[r][q] = sbase[(c * ITH + S * y0 + r) * RS
                                     + (XOFF - 1) + S * tx + q];
#pragma unroll
            for (int og = 0; og < OUTG; og++) {
                float wv[9];
#pragma unroll
                for (int k = 0; k < 9; k++) wv[k] = s_w[og][c][k];
#pragma unroll
                for (int p = 0; p < PIX; p++)
#pragma unroll
                    for (int ky = 0; ky < 3; ky++)
#pragma unroll
                        for (int kx = 0; kx < 3; kx++)
                            acc[p][og] = fmaf(iv[S * p + ky][kx],
                                              wv[ky * 3 + kx], acc[p][og]);
            }
        }
    }

    const int bb = blockIdx.y * IMGS + im;
    const int x  = x0 + tx;
#pragma unroll
    for (int og = 0; og < OUTG; og++) {
        const int oc = oc0 + og;
        const float bv = bias[oc];
#pragma unroll
        for (int p = 0; p < PIX; p++) {
            const int y = y0 + p;
            float v = acc[p][og] + bv;
            const size_t sp = (size_t)y * OW + x;
            out0[((size_t)bb * Cout + oc) * (OH * OW) + sp] =
                v > 0.f ? v : 0.2f * v;
        }
    }
    (void)zb; (void)hprev; (void)out1;
}

// ---------------------------------------------------------------------------
// GRU conv template: stride 1, square OHxOH, PIX=4 rows x 2 cols x 4 ocs per
// thread, f32x2 FMA, cp.async double-buffered channel pipeline (CHUNK=2).
//   MODE 1: s=sigmoid(v); oc<hid -> rh=s*h ; else z=s
//   MODE 2: c=tanh(v); out0 = z*h + (1-z)*c
// ---------------------------------------------------------------------------
template<int OH, int TLW, int IMGS, int CHUNK, int MODE>
__global__ void __launch_bounds__(TLW*(OH/4)*IMGS, 2)
gru_conv(const float* __restrict__ in0, int C0,
         const float* __restrict__ in1, int C1,
         const float2* __restrict__ wdup, const float* __restrict__ bias,
         const float* __restrict__ zb,  const float* __restrict__ hprev,
         float* __restrict__ out0, float* __restrict__ out1, int Cout)
{
    constexpr int NT    = TLW * (OH / 4) * IMGS;
    constexpr int ITH   = OH + 2;
    constexpr int W_INT = 2 * TLW;            // tile width (in/out cols)
    constexpr int RS    = pick_rs(W_INT + 5, 4);
    constexpr int NSEG  = W_INT / 16;
    constexpr int R     = IMGS * CHUNK * ITH;
    constexpr int BUF   = IMGS * CHUNK * ITH * RS;

    __shared__ __align__(16) float  s_in[2][BUF];
    __shared__ __align__(16) float2 s_w2[2][4][CHUNK][10];  // 9 used + pad

    const int tid = threadIdx.x;
    const int tx  = tid % TLW;
    const int ty  = (tid / TLW) % (OH / 4);
    const int im  = tid / (TLW * (OH / 4));
    const int y0  = ty * 4;
    const int x0w = blockIdx.x * W_INT;
    const int oc0 = blockIdx.z * 4;
    const int bbase = blockIdx.y * IMGS;
    const int Ctot = C0 + C1;
    const int Ceff = in1 ? Ctot : C0;
    const int nch  = Ceff / CHUNK;

    auto load_chunk = [&](int cc0, int buf) {
        // weights: (w,w) pairs, 8B cp.async each
        for (int i = tid; i < 4 * CHUNK * 9; i += NT) {
            int k = i % 9; int t2 = i / 9;
            int c = t2 % CHUNK; int og = t2 / CHUNK;
            uint32_t dst = (uint32_t)__cvta_generic_to_shared(&s_w2[buf][og][c][k]);
            cp8(dst, wdup + ((size_t)(oc0 + og) * Ctot + cc0 + c) * 9 + k);
        }
        // interior rows, 16B cp.async, zero-fill out-of-range rows
        for (int u = tid; u < R * NSEG; u += NT) {
            const int row = u / NSEG;
            const int seg = u - row * NSEG;
            const int yy  = row % ITH;
            const int t2  = row / ITH;
            const int c   = t2 % CHUNK;
            const int imm = t2 / CHUNK;
            const int gy  = yy - 1;
            const int ci  = cc0 + c;
            const int bb  = bbase + imm;
            const float* p; int ch, Cc;
            if (ci < C0) { p = in0; ch = ci; Cc = C0; }
            else         { p = in1; ch = ci - C0; Cc = C1; }
            const bool rv = (unsigned)gy < (unsigned)OH;
            const float* gp = p + (((size_t)bb * Cc + ch) * OH + (rv ? gy : 0)) * OH
                                + x0w + seg * 16;
            uint32_t dst = (uint32_t)__cvta_generic_to_shared(
                &s_in[buf][((imm * CHUNK + c) * ITH + yy) * RS + 4 + seg * 16]);
            const int sz = rv ? 16 : 0;
            cp16(dst,      gp,      sz);
            cp16(dst + 16, gp + 4,  sz);
            cp16(dst + 32, gp + 8,  sz);
            cp16(dst + 48, gp + 12, sz);
        }
        // halo columns
        for (int row = tid; row < R; row += NT) {
            const int yy  = row % ITH;
            const int t2  = row / ITH;
            const int c   = t2 % CHUNK;
            const int imm = t2 / CHUNK;
            const int gy  = yy - 1;
            const int ci  = cc0 + c;
            const int bb  = bbase + imm;
            const float* p; int ch, Cc;
            if (ci < C0) { p = in0; ch = ci; Cc = C0; }
            else         { p = in1; ch = ci - C0; Cc = C1; }
            const bool rv = (unsigned)gy < (unsigned)OH;
            const float* rb = p + (((size_t)bb * Cc + ch) * OH + (rv ? gy : 0)) * OH;
            const int gxl = x0w - 1, gxr = x0w + W_INT;
            const bool lv = rv && gxl >= 0;
            const bool rvv = rv && gxr < OH;
            uint32_t dr = (uint32_t)__cvta_generic_to_shared(
                &s_in[buf][((imm * CHUNK + c) * ITH + yy) * RS]);
            cp4(dr + 3 * 4,           rb + (lv ? gxl : 0), lv ? 4 : 0);
            cp4(dr + (4 + W_INT) * 4, rb + (rvv ? gxr : 0), rvv ? 4 : 0);
        }
    };

    unsigned long long acc[4][4];
#pragma unroll
    for (int p = 0; p < 4; p++)
#pragma unroll
        for (int og = 0; og < 4; og++) acc[p][og] = 0ull;

    load_chunk(0, 0); CP_COMMIT();

    for (int k = 0; k < nch; k++) {
        if (k + 1 < nch) { load_chunk((k + 1) * CHUNK, (k + 1) & 1); CP_COMMIT(); cp_wait<1>(); }
        else             { cp_wait<0>(); }
        __syncthreads();

        const int b2 = k & 1;
        const float* sb = &s_in[b2][(im * CHUNK) * ITH * RS];
#pragma unroll
        for (int c = 0; c < CHUNK; c++) {
            unsigned long long pr[6][3];
#pragma unroll
            for (int r = 0; r < 6; r++) {
                const float* rowp = sb + (c * ITH + y0 + r) * RS + 3 + 2 * tx;
                float v0 = rowp[0], v1 = rowp[1], v2 = rowp[2], v3 = rowp[3];
                pr[r][0] = packf2(v0, v1);
                pr[r][1] = packf2(v1, v2);
                pr[r][2] = packf2(v2, v3);
            }
#pragma unroll
            for (int og = 0; og < 4; og++) {
                const unsigned long long* wp =
                    reinterpret_cast<const unsigned long long*>(&s_w2[b2][og][c][0]);
                unsigned long long w[9];
#pragma unroll
                for (int q = 0; q < 9; q++) w[q] = wp[q];
#pragma unroll
                for (int p = 0; p < 4; p++)
#pragma unroll
                    for (int ky = 0; ky < 3; ky++)
#pragma unroll
                        for (int kx = 0; kx < 3; kx++)
                            ffma2(acc[p][og], pr[p + ky][kx], w[ky * 3 + kx]);
            }
        }
        __syncthreads();
    }

    // ---- epilogue (2 cols -> float2 I/O, 8B aligned since x even) ----
    const int bb = bbase + im;
    const int x  = x0w + 2 * tx;
#pragma unroll
    for (int og = 0; og < 4; og++) {
        const int oc = oc0 + og;
        const float bv = bias[oc];
#pragma unroll
        for (int p = 0; p < 4; p++) {
            float2 v = unpk(acc[p][og]);
            v.x += bv; v.y += bv;
            const size_t sp = (size_t)(y0 + p) * OH + x;
            if (MODE == 1) {
                const int hid = Cout >> 1;
                float2 s = make_float2(1.f / (1.f + __expf(-v.x)),
                                       1.f / (1.f + __expf(-v.y)));
                if (oc < hid) {
                    const size_t idx = ((size_t)bb * hid + oc) * (OH * OH) + sp;
                    float2 h = hprev ? *(const float2*)(hprev + idx)
                                     : make_float2(0.f, 0.f);
                    *(float2*)(out0 + idx) = make_float2(s.x * h.x, s.y * h.y);
                } else {
                    const size_t idx = ((size_t)bb * hid + (oc - hid)) * (OH * OH) + sp;
                    *(float2*)(out1 + idx) = s;
                }
            } else {
                const size_t idx = ((size_t)bb * Cout + oc) * (OH * OH) + sp;
                float2 z = *(const float2*)(zb + idx);
                float2 h = hprev ? *(const float2*)(hprev + idx)
                                 : make_float2(0.f, 0.f);
                *(float2*)(out0 + idx) = make_float2(
                    z.x * h.x + (1.f - z.x) * tanhf(v.x),
                    z.y * h.y + (1.f - z.y) * tanhf(v.y));
            }
        }
    }
}

// ---------------------------------------------------------------------------
extern "C" void kernel_launch(void* const* d_in, const int* in_sizes, int n_in,
                              void* d_out, int out_size)
{
    (void)in_sizes; (void)n_in; (void)out_size;
    const float* x   = (const float*)d_in[0];
    const float* W1  = (const float*)d_in[1];   const float* b1  = (const float*)d_in[2];
    const float* Wg1 = (const float*)d_in[3];   const float* bg1 = (const float*)d_in[4];
    const float* Wc1 = (const float*)d_in[5];   const float* bc1 = (const float*)d_in[6];
    const float* W2  = (const float*)d_in[7];   const float* b2  = (const float*)d_in[8];
    const float* Wg2 = (const float*)d_in[9];   const float* bg2 = (const float*)d_in[10];
    const float* Wc2 = (const float*)d_in[11];  const float* bc2 = (const float*)d_in[12];
    const float* W3  = (const float*)d_in[13];  const float* b3  = (const float*)d_in[14];
    const float* Wg3 = (const float*)d_in[15];  const float* bg3 = (const float*)d_in[16];
    const float* Wc3 = (const float*)d_in[17];  const float* bc3 = (const float*)d_in[18];

    float *feat1, *outs1, *feat2, *outs2, *feat3, *outs3, *rh, *zb;
    float2* wd;
    cudaGetSymbolAddress((void**)&feat1, g_feat1);
    cudaGetSymbolAddress((void**)&outs1, g_outs1);
    cudaGetSymbolAddress((void**)&feat2, g_feat2);
    cudaGetSymbolAddress((void**)&outs2, g_outs2);
    cudaGetSymbolAddress((void**)&feat3, g_feat3);
    cudaGetSymbolAddress((void**)&outs3, g_outs3);
    cudaGetSymbolAddress((void**)&rh,    g_rh);
    cudaGetSymbolAddress((void**)&zb,    g_zb);
    cudaGetSymbolAddress((void**)&wd,    g_wdup);

    // weight duplication offsets (float2 elements)
    const size_t o_g1 = 0,       n_g1 = 128u*80*9;   // 92160
    const size_t o_c1 = 92160,   n_c1 = 64u*80*9;    // 46080
    const size_t o_g2 = 138240,  n_g2 = 192u*160*9;  // 276480
    const size_t o_c2 = 414720,  n_c2 = 96u*160*9;   // 138240
    const size_t o_g3 = 552960,  n_g3 = 192u*192*9;  // 331776
    const size_t o_c3 = 884736,  n_c3 = 96u*192*9;   // 165888

    dup_w<<<(int)((n_g1+255)/256),256>>>(Wg1, wd+o_g1, (int)n_g1);
    dup_w<<<(int)((n_c1+255)/256),256>>>(Wc1, wd+o_c1, (int)n_c1);
    dup_w<<<(int)((n_g2+255)/256),256>>>(Wg2, wd+o_g2, (int)n_g2);
    dup_w<<<(int)((n_c2+255)/256),256>>>(Wc2, wd+o_c2, (int)n_c2);
    dup_w<<<(int)((n_g3+255)/256),256>>>(Wg3, wd+o_g3, (int)n_g3);
    dup_w<<<(int)((n_c3+255)/256),256>>>(Wc3, wd+o_c3, (int)n_c3);

    float* out = (float*)d_out;

    // ======================= Stage 1: 128 -> 64, hid 64 ====================
    conv3x3_k<64,64,128,128,2,16,4,1,4,1,0><<<dim3(4,80,4),256>>>(
        x,1, nullptr,0, W1,b1, nullptr,nullptr, feat1,nullptr, 16, 1);

    for (int t = 0; t < 10; t++) {
        const float* ft = feat1 + (size_t)t * 8 * 16 * 64 * 64;
        const float* hp = t ? outs1 + (size_t)(t-1) * 8 * 64 * 64 * 64 : nullptr;
        float*       ho = outs1 + (size_t)t * 8 * 64 * 64 * 64;
        gru_conv<64,16,1,2,1><<<dim3(2,8,32),256>>>(
            ft,16, hp,64, wd+o_g1, bg1, nullptr, hp, rh, zb, 128);
        gru_conv<64,16,1,2,2><<<dim3(2,8,16),256>>>(
            ft,16, rh,64, wd+o_c1, bc1, zb, hp, ho, nullptr, 64);
    }
    cudaMemcpyAsync(out, outs1 + (size_t)9 * 8 * 64 * 64 * 64,
                    (size_t)8 * 64 * 64 * 64 * sizeof(float),
                    cudaMemcpyDeviceToDevice);

    // ======================= Stage 2: 64 -> 32, hid 96 =====================
    conv3x3_k<32,32,64,64,2,32,4,1,4,1,0><<<dim3(1,80,16),256>>>(
        outs1,64, nullptr,0, W2,b2, nullptr,nullptr, feat2,nullptr, 64, 0);

    for (int t = 0; t < 10; t++) {
        const float* ft = feat2 + (size_t)t * 8 * 64 * 32 * 32;
        const float* hp = t ? outs2 + (size_t)(t-1) * 8 * 96 * 32 * 32 : nullptr;
        float*       ho = outs2 + (size_t)t * 8 * 96 * 32 * 32;
        gru_conv<32,16,1,2,1><<<dim3(1,8,48),128>>>(
            ft,64, hp,96, wd+o_g2, bg2, nullptr, hp, rh, zb, 192);
        gru_conv<32,16,1,2,2><<<dim3(1,8,24),128>>>(
            ft,64, rh,96, wd+o_c2, bc2, zb, hp, ho, nullptr, 96);
    }
    cudaMemcpyAsync(out + 2097152, outs2 + (size_t)9 * 8 * 96 * 32 * 32,
                    (size_t)8 * 96 * 32 * 32 * sizeof(float),
                    cudaMemcpyDeviceToDevice);

    // ======================= Stage 3: 32 -> 16, hid 96 =====================
    conv3x3_k<16,16,32,32,2,16,4,4,4,1,0><<<dim3(1,20,24),256>>>(
        outs2,96, nullptr,0, W3,b3, nullptr,nullptr, feat3,nullptr, 96, 0);

    for (int t = 0; t < 10; t++) {
        const float* ft = feat3 + (size_t)t * 8 * 96 * 16 * 16;
        const float* hp = t ? outs3 + (size_t)(t-1) * 8 * 96 * 16 * 16 : nullptr;
        float*       ho = outs3 + (size_t)t * 8 * 96 * 16 * 16;
        gru_conv<16,8,4,2,1><<<dim3(1,2,48),128>>>(
            ft,96, hp,96, wd+o_g3, bg3, nullptr, hp, rh, zb, 192);
        gru_conv<16,8,4,2,2><<<dim3(1,2,24),128>>>(
            ft,96, rh,96, wd+o_c3, bc3, zb, hp, ho, nullptr, 96);
    }
    cudaMemcpyAsync(out + 2883584, outs3 + (size_t)9 * 8 * 96 * 16 * 16,
                    (size_t)8 * 96 * 16 * 16 * sizeof(float),
                    cudaMemcpyDeviceToDevice);
}

// round 14
// speedup vs baseline: 2.4754x; 1.0025x over previous
#include <cuda_runtime.h>
#include <cstdint>
#include <math.h>

// ---------------------------------------------------------------------------
// Scratch buffers (no cudaMalloc allowed). (T*B, C, H, W), batch = t*8 + b.
// ---------------------------------------------------------------------------
__device__ __align__(16) float g_feat1[80u * 16 * 64 * 64];
__device__ __align__(16) float g_outs1[80u * 64 * 64 * 64];
__device__ __align__(16) float g_feat2[80u * 64 * 32 * 32];
__device__ __align__(16) float g_outs2[80u * 96 * 32 * 32];
__device__ __align__(16) float g_feat3[80u * 96 * 16 * 16];
__device__ __align__(16) float g_outs3[80u * 96 * 16 * 16];
__device__ __align__(16) float g_rh   [8u * 64 * 64 * 64];
__device__ __align__(16) float g_zb   [8u * 64 * 64 * 64];
// duplicated (w,w) weights for the 6 GRU convs, expanded at launch
__device__ __align__(16) float2 g_wdup[1050624];

__host__ __device__ constexpr int pick_rs(int base, int dy) {
    int r = (base + 3) & ~3;
    for (int i = 0; i < 8; i++) { if ((dy * r) % 32 == 16) return r; r += 4; }
    return (base + 3) & ~3;
}

// ---------------- cp.async / f32x2 helpers ---------------------------------
__device__ __forceinline__ void cp16(uint32_t d, const void* s, int sz) {
    asm volatile("cp.async.ca.shared.global [%0], [%1], 16, %2;"
                 :: "r"(d), "l"(s), "r"(sz));
}
__device__ __forceinline__ void cp8(uint32_t d, const void* s) {
    asm volatile("cp.async.ca.shared.global [%0], [%1], 8;"
                 :: "r"(d), "l"(s));
}
__device__ __forceinline__ void cp4(uint32_t d, const void* s, int sz) {
    asm volatile("cp.async.ca.shared.global [%0], [%1], 4, %2;"
                 :: "r"(d), "l"(s), "r"(sz));
}
#define CP_COMMIT() asm volatile("cp.async.commit_group;" ::: "memory")
template<int N> __device__ __forceinline__ void cp_wait() {
    asm volatile("cp.async.wait_group %0;" :: "n"(N) : "memory");
}
__device__ __forceinline__ unsigned long long packf2(float lo, float hi) {
    unsigned long long r;
    asm("mov.b64 %0, {%1, %2};" : "=l"(r) : "f"(lo), "f"(hi));
    return r;
}
__device__ __forceinline__ float2 unpk(unsigned long long v) {
    float2 r;
    asm("mov.b64 {%0, %1}, %2;" : "=f"(r.x), "=f"(r.y) : "l"(v));
    return r;
}
__device__ __forceinline__ void ffma2(unsigned long long& d,
                                      unsigned long long a, unsigned long long b) {
    asm("fma.rn.f32x2 %0, %1, %2, %0;" : "+l"(d) : "l"(a), "l"(b));
}

// Single-launch weight duplication for all 6 GRU convs: w[i] -> (w[i], w[i])
__global__ void dup_all(const float* __restrict__ s0, const float* __restrict__ s1,
                        const float* __restrict__ s2, const float* __restrict__ s3,
                        const float* __restrict__ s4, const float* __restrict__ s5,
                        float2* __restrict__ o)
{
    int i = blockIdx.x * 256 + threadIdx.x;
    const float* p; int off;
    if      (i < 92160)   { p = s0; off = 0; }
    else if (i < 138240)  { p = s1; off = 92160; }
    else if (i < 414720)  { p = s2; off = 138240; }
    else if (i < 552960)  { p = s3; off = 414720; }
    else if (i < 884736)  { p = s4; off = 552960; }
    else if (i < 1050624) { p = s5; off = 884736; }
    else return;
    float v = p[i - off];
    o[i] = make_float2(v, v);
}

// ---------------------------------------------------------------------------
// Stem template (stride-2 conv, leaky_relu) — proven R9 path, unchanged.
// ---------------------------------------------------------------------------
template<int OH, int OW, int IH, int IW, int S, int TLW,
         int PIX, int IMGS, int OUTG, int CHUNK, int MODE>
__global__ void __launch_bounds__(TLW*(OH/PIX)*IMGS)
conv3x3_k(const float* __restrict__ in0, int C0,
          const float* __restrict__ in1, int C1,
          const float* __restrict__ wgt, const float* __restrict__ bias,
          const float* __restrict__ zb,  const float* __restrict__ hprev,
          float* __restrict__ out0, float* __restrict__ out1,
          int Cout, int xpose)
{
    constexpr int NT    = TLW * (OH / PIX) * IMGS;
    constexpr int ITH   = S * OH + 2;
    constexpr int W_INT = S * TLW;
    constexpr int IVR   = S * (PIX - 1) + 3;
    constexpr int DY    = S * PIX;
    constexpr int RS    = pick_rs(W_INT + 5, DY);
    constexpr int XOFF  = 4;
    constexpr int SEGW  = (W_INT <= 16) ? W_INT : 16;
    constexpr int NSEG  = W_INT / SEGW;
    constexpr int R     = IMGS * CHUNK * ITH;
    constexpr int U     = R * NSEG;

    __shared__ __align__(16) float s_in[IMGS * CHUNK * ITH * RS];
    __shared__ float s_w[OUTG][CHUNK][9];

    const int tid = threadIdx.x;
    const int tx  = tid % TLW;
    const int ty  = (tid / TLW) % (OH / PIX);
    const int im  = tid / (TLW * (OH / PIX));
    const int y0  = ty * PIX;
    const int x0  = blockIdx.x * TLW;
    const int oc0 = blockIdx.z * OUTG;
    const int Ctot = C0 + C1;
    const int Ceff = in1 ? Ctot : C0;

    float acc[PIX][OUTG];
#pragma unroll
    for (int p = 0; p < PIX; p++)
#pragma unroll
        for (int og = 0; og < OUTG; og++) acc[p][og] = 0.f;

    for (int cc0 = 0; cc0 < Ceff; cc0 += CHUNK) {
        __syncthreads();
        for (int i = tid; i < OUTG * CHUNK * 9; i += NT) {
            int k = i % 9; int t2 = i / 9;
            int c = t2 % CHUNK; int og = t2 / CHUNK;
            s_w[og][c][k] = wgt[((size_t)(oc0 + og) * Ctot + cc0 + c) * 9 + k];
        }
        for (int u = tid; u < U; u += NT) {
            const int row = u / NSEG;
            const int seg = u - row * NSEG;
            const int yy  = row % ITH;
            const int t2  = row / ITH;
            const int c   = t2 % CHUNK;
            const int imm = t2 / CHUNK;
            const int gy  = yy - 1;
            const int ci  = cc0 + c;
            int bb = blockIdx.y * IMGS + imm;
            const float* p; int ch, Cc;
            if (ci < C0) {
                p = in0; ch = ci; Cc = C0;
                if (xpose) bb = (bb & 7) * 10 + (bb >> 3);
            } else { p = in1; ch = ci - C0; Cc = C1; }
            const bool rv = (unsigned)gy < (unsigned)IH;
            const float4* gp = (const float4*)
                (p + (((size_t)bb * Cc + ch) * IH + gy) * IW + S * x0 + seg * SEGW);
            float* sp = &s_in[((imm * CHUNK + c) * ITH + yy) * RS + XOFF + seg * SEGW];
#pragma unroll
            for (int k = 0; k < SEGW / 4; k++) {
                float4 v = rv ? gp[k] : make_float4(0.f, 0.f, 0.f, 0.f);
                *(float4*)(sp + 4 * k) = v;
            }
        }
        for (int row = tid; row < R; row += NT) {
            const int yy  = row % ITH;
            const int t2  = row / ITH;
            const int c   = t2 % CHUNK;
            const int imm = t2 / CHUNK;
            const int gy  = yy - 1;
            const int ci  = cc0 + c;
            int bb = blockIdx.y * IMGS + imm;
            const float* p; int ch, Cc;
            if (ci < C0) {
                p = in0; ch = ci; Cc = C0;
                if (xpose) bb = (bb & 7) * 10 + (bb >> 3);
            } else { p = in1; ch = ci - C0; Cc = C1; }
            const bool rv = (unsigned)gy < (unsigned)IH;
            const float* rb = p + (((size_t)bb * Cc + ch) * IH + gy) * IW;
            const int gxl = S * x0 - 1, gxr = S * x0 + W_INT;
            float* sr = &s_in[((imm * CHUNK + c) * ITH + yy) * RS];
            sr[XOFF - 1]     = (rv && gxl >= 0) ? rb[gxl] : 0.f;
            sr[XOFF + W_INT] = (rv && gxr < IW) ? rb[gxr] : 0.f;
        }
        __syncthreads();

        const float* sbase = &s_in[(im * CHUNK) * ITH * RS];
#pragma unroll
        for (int c = 0; c < CHUNK; c++) {
            float iv[IVR][3];
#pragma unroll
            for (int r = 0; r < IVR; r++)
#pragma unroll
                for (int q = 0; q < 3; q++)
                    iv[r][q] = sbase[(c * ITH + S * y0 + r) * RS
                                     + (XOFF - 1) + S * tx + q];
#pragma unroll
            for (int og = 0; og < OUTG; og++) {
                float wv[9];
#pragma unroll
                for (int k = 0; k < 9; k++) wv[k] = s_w[og][c][k];
#pragma unroll
                for (int p = 0; p < PIX; p++)
#pragma unroll
                    for (int ky = 0; ky < 3; ky++)
#pragma unroll
                        for (int kx = 0; kx < 3; kx++)
                            acc[p][og] = fmaf(iv[S * p + ky][kx],
                                              wv[ky * 3 + kx], acc[p][og]);
            }
        }
    }

    const int bb = blockIdx.y * IMGS + im;
    const int x  = x0 + tx;
#pragma unroll
    for (int og = 0; og < OUTG; og++) {
        const int oc = oc0 + og;
        const float bv = bias[oc];
#pragma unroll
        for (int p = 0; p < PIX; p++) {
            const int y = y0 + p;
            float v = acc[p][og] + bv;
            const size_t sp = (size_t)y * OW + x;
            out0[((size_t)bb * Cout + oc) * (OH * OW) + sp] =
                v > 0.f ? v : 0.2f * v;
        }
    }
    (void)zb; (void)hprev; (void)out1;
}

// ---------------------------------------------------------------------------
// GRU conv template: stride 1, square OHxOH, PIX=4 rows x 2 cols x 4 ocs per
// thread, f32x2 FMA, cp.async double-buffered channel pipeline (CHUNK=2).
//   MODE 1: s=sigmoid(v); oc<hid -> rh=s*h ; else z=s
//   MODE 2: c=tanh(v); out0 = z*h + (1-z)*c
// ---------------------------------------------------------------------------
template<int OH, int TLW, int IMGS, int CHUNK, int MODE>
__global__ void __launch_bounds__(TLW*(OH/4)*IMGS, 2)
gru_conv(const float* __restrict__ in0, int C0,
         const float* __restrict__ in1, int C1,
         const float2* __restrict__ wdup, const float* __restrict__ bias,
         const float* __restrict__ zb,  const float* __restrict__ hprev,
         float* __restrict__ out0, float* __restrict__ out1, int Cout)
{
    constexpr int NT    = TLW * (OH / 4) * IMGS;
    constexpr int ITH   = OH + 2;
    constexpr int W_INT = 2 * TLW;            // tile width (in/out cols)
    constexpr int RS    = pick_rs(W_INT + 5, 4);
    constexpr int NSEG  = W_INT / 16;
    constexpr int R     = IMGS * CHUNK * ITH;
    constexpr int BUF   = IMGS * CHUNK * ITH * RS;

    __shared__ __align__(16) float  s_in[2][BUF];
    __shared__ __align__(16) float2 s_w2[2][4][CHUNK][10];  // 9 used + pad

    const int tid = threadIdx.x;
    const int tx  = tid % TLW;
    const int ty  = (tid / TLW) % (OH / 4);
    const int im  = tid / (TLW * (OH / 4));
    const int y0  = ty * 4;
    const int x0w = blockIdx.x * W_INT;
    const int oc0 = blockIdx.z * 4;
    const int bbase = blockIdx.y * IMGS;
    const int Ctot = C0 + C1;
    const int Ceff = in1 ? Ctot : C0;
    const int nch  = Ceff / CHUNK;

    auto load_chunk = [&](int cc0, int buf) {
        // weights: (w,w) pairs, 8B cp.async each
        for (int i = tid; i < 4 * CHUNK * 9; i += NT) {
            int k = i % 9; int t2 = i / 9;
            int c = t2 % CHUNK; int og = t2 / CHUNK;
            uint32_t dst = (uint32_t)__cvta_generic_to_shared(&s_w2[buf][og][c][k]);
            cp8(dst, wdup + ((size_t)(oc0 + og) * Ctot + cc0 + c) * 9 + k);
        }
        // interior rows, 16B cp.async, zero-fill out-of-range rows
        for (int u = tid; u < R * NSEG; u += NT) {
            const int row = u / NSEG;
            const int seg = u - row * NSEG;
            const int yy  = row % ITH;
            const int t2  = row / ITH;
            const int c   = t2 % CHUNK;
            const int imm = t2 / CHUNK;
            const int gy  = yy - 1;
            const int ci  = cc0 + c;
            const int bb  = bbase + imm;
            const float* p; int ch, Cc;
            if (ci < C0) { p = in0; ch = ci; Cc = C0; }
            else         { p = in1; ch = ci - C0; Cc = C1; }
            const bool rv = (unsigned)gy < (unsigned)OH;
            const float* gp = p + (((size_t)bb * Cc + ch) * OH + (rv ? gy : 0)) * OH
                                + x0w + seg * 16;
            uint32_t dst = (uint32_t)__cvta_generic_to_shared(
                &s_in[buf][((imm * CHUNK + c) * ITH + yy) * RS + 4 + seg * 16]);
            const int sz = rv ? 16 : 0;
            cp16(dst,      gp,      sz);
            cp16(dst + 16, gp + 4,  sz);
            cp16(dst + 32, gp + 8,  sz);
            cp16(dst + 48, gp + 12, sz);
        }
        // halo columns
        for (int row = tid; row < R; row += NT) {
            const int yy  = row % ITH;
            const int t2  = row / ITH;
            const int c   = t2 % CHUNK;
            const int imm = t2 / CHUNK;
            const int gy  = yy - 1;
            const int ci  = cc0 + c;
            const int bb  = bbase + imm;
            const float* p; int ch, Cc;
            if (ci < C0) { p = in0; ch = ci; Cc = C0; }
            else         { p = in1; ch = ci - C0; Cc = C1; }
            const bool rv = (unsigned)gy < (unsigned)OH;
            const float* rb = p + (((size_t)bb * Cc + ch) * OH + (rv ? gy : 0)) * OH;
            const int gxl = x0w - 1, gxr = x0w + W_INT;
            const bool lv = rv && gxl >= 0;
            const bool rvv = rv && gxr < OH;
            uint32_t dr = (uint32_t)__cvta_generic_to_shared(
                &s_in[buf][((imm * CHUNK + c) * ITH + yy) * RS]);
            cp4(dr + 3 * 4,           rb + (lv ? gxl : 0), lv ? 4 : 0);
            cp4(dr + (4 + W_INT) * 4, rb + (rvv ? gxr : 0), rvv ? 4 : 0);
        }
    };

    unsigned long long acc[4][4];
#pragma unroll
    for (int p = 0; p < 4; p++)
#pragma unroll
        for (int og = 0; og < 4; og++) acc[p][og] = 0ull;

    load_chunk(0, 0); CP_COMMIT();

    for (int k = 0; k < nch; k++) {
        if (k + 1 < nch) { load_chunk((k + 1) * CHUNK, (k + 1) & 1); CP_COMMIT(); cp_wait<1>(); }
        else             { cp_wait<0>(); }
        __syncthreads();

        const int b2 = k & 1;
        const float* sb = &s_in[b2][(im * CHUNK) * ITH * RS];
#pragma unroll
        for (int c = 0; c < CHUNK; c++) {
            unsigned long long pr[6][3];
#pragma unroll
            for (int r = 0; r < 6; r++) {
                // cols 2tx-1 .. 2tx+2: scalar + aligned LDS.64 + scalar
                const float* rowp = sb + (c * ITH + y0 + r) * RS + 3 + 2 * tx;
                float  v0  = rowp[0];
                float2 v12 = *(const float2*)(rowp + 1);   // 8B-aligned
                float  v3  = rowp[3];
                pr[r][0] = packf2(v0,    v12.x);
                pr[r][1] = packf2(v12.x, v12.y);
                pr[r][2] = packf2(v12.y, v3);
            }
#pragma unroll
            for (int og = 0; og < 4; og++) {
                const unsigned long long* wp =
                    reinterpret_cast<const unsigned long long*>(&s_w2[b2][og][c][0]);
                unsigned long long w[9];
#pragma unroll
                for (int q = 0; q < 9; q++) w[q] = wp[q];
#pragma unroll
                for (int p = 0; p < 4; p++)
#pragma unroll
                    for (int ky = 0; ky < 3; ky++)
#pragma unroll
                        for (int kx = 0; kx < 3; kx++)
                            ffma2(acc[p][og], pr[p + ky][kx], w[ky * 3 + kx]);
            }
        }
        __syncthreads();
    }

    // ---- epilogue (2 cols -> float2 I/O, 8B aligned since x even) ----
    const int bb = bbase + im;
    const int x  = x0w + 2 * tx;
#pragma unroll
    for (int og = 0; og < 4; og++) {
        const int oc = oc0 + og;
        const float bv = bias[oc];
#pragma unroll
        for (int p = 0; p < 4; p++) {
            float2 v = unpk(acc[p][og]);
            v.x += bv; v.y += bv;
            const size_t sp = (size_t)(y0 + p) * OH + x;
            if (MODE == 1) {
                const int hid = Cout >> 1;
                float2 s = make_float2(1.f / (1.f + __expf(-v.x)),
                                       1.f / (1.f + __expf(-v.y)));
                if (oc < hid) {
                    const size_t idx = ((size_t)bb * hid + oc) * (OH * OH) + sp;
                    float2 h = hprev ? *(const float2*)(hprev + idx)
                                     : make_float2(0.f, 0.f);
                    *(float2*)(out0 + idx) = make_float2(s.x * h.x, s.y * h.y);
                } else {
                    const size_t idx = ((size_t)bb * hid + (oc - hid)) * (OH * OH) + sp;
                    *(float2*)(out1 + idx) = s;
                }
            } else {
                const size_t idx = ((size_t)bb * Cout + oc) * (OH * OH) + sp;
                float2 z = *(const float2*)(zb + idx);
                float2 h = hprev ? *(const float2*)(hprev + idx)
                                 : make_float2(0.f, 0.f);
                *(float2*)(out0 + idx) = make_float2(
                    z.x * h.x + (1.f - z.x) * tanhf(v.x),
                    z.y * h.y + (1.f - z.y) * tanhf(v.y));
            }
        }
    }
}

// ---------------------------------------------------------------------------
extern "C" void kernel_launch(void* const* d_in, const int* in_sizes, int n_in,
                              void* d_out, int out_size)
{
    (void)in_sizes; (void)n_in; (void)out_size;
    const float* x   = (const float*)d_in[0];
    const float* W1  = (const float*)d_in[1];   const float* b1  = (const float*)d_in[2];
    const float* Wg1 = (const float*)d_in[3];   const float* bg1 = (const float*)d_in[4];
    const float* Wc1 = (const float*)d_in[5];   const float* bc1 = (const float*)d_in[6];
    const float* W2  = (const float*)d_in[7];   const float* b2  = (const float*)d_in[8];
    const float* Wg2 = (const float*)d_in[9];   const float* bg2 = (const float*)d_in[10];
    const float* Wc2 = (const float*)d_in[11];  const float* bc2 = (const float*)d_in[12];
    const float* W3  = (const float*)d_in[13];  const float* b3  = (const float*)d_in[14];
    const float* Wg3 = (const float*)d_in[15];  const float* bg3 = (const float*)d_in[16];
    const float* Wc3 = (const float*)d_in[17];  const float* bc3 = (const float*)d_in[18];

    float *feat1, *outs1, *feat2, *outs2, *feat3, *outs3, *rh, *zb;
    float2* wd;
    cudaGetSymbolAddress((void**)&feat1, g_feat1);
    cudaGetSymbolAddress((void**)&outs1, g_outs1);
    cudaGetSymbolAddress((void**)&feat2, g_feat2);
    cudaGetSymbolAddress((void**)&outs2, g_outs2);
    cudaGetSymbolAddress((void**)&feat3, g_feat3);
    cudaGetSymbolAddress((void**)&outs3, g_outs3);
    cudaGetSymbolAddress((void**)&rh,    g_rh);
    cudaGetSymbolAddress((void**)&zb,    g_zb);
    cudaGetSymbolAddress((void**)&wd,    g_wdup);

    // weight duplication offsets (float2 elements)
    const size_t o_g1 = 0;
    const size_t o_c1 = 92160;
    const size_t o_g2 = 138240;
    const size_t o_c2 = 414720;
    const size_t o_g3 = 552960;
    const size_t o_c3 = 884736;

    dup_all<<<(1050624 + 255) / 256, 256>>>(Wg1, Wc1, Wg2, Wc2, Wg3, Wc3, wd);

    float* out = (float*)d_out;

    // ======================= Stage 1: 128 -> 64, hid 64 ====================
    conv3x3_k<64,64,128,128,2,16,4,1,4,1,0><<<dim3(4,80,4),256>>>(
        x,1, nullptr,0, W1,b1, nullptr,nullptr, feat1,nullptr, 16, 1);

    for (int t = 0; t < 10; t++) {
        const float* ft = feat1 + (size_t)t * 8 * 16 * 64 * 64;
        const float* hp = t ? outs1 + (size_t)(t-1) * 8 * 64 * 64 * 64 : nullptr;
        float*       ho = outs1 + (size_t)t * 8 * 64 * 64 * 64;
        gru_conv<64,16,1,2,1><<<dim3(2,8,32),256>>>(
            ft,16, hp,64, wd+o_g1, bg1, nullptr, hp, rh, zb, 128);
        gru_conv<64,16,1,2,2><<<dim3(2,8,16),256>>>(
            ft,16, rh,64, wd+o_c1, bc1, zb, hp, ho, nullptr, 64);
    }
    cudaMemcpyAsync(out, outs1 + (size_t)9 * 8 * 64 * 64 * 64,
                    (size_t)8 * 64 * 64 * 64 * sizeof(float),
                    cudaMemcpyDeviceToDevice);

    // ======================= Stage 2: 64 -> 32, hid 96 =====================
    conv3x3_k<32,32,64,64,2,32,4,1,4,1,0><<<dim3(1,80,16),256>>>(
        outs1,64, nullptr,0, W2,b2, nullptr,nullptr, feat2,nullptr, 64, 0);

    for (int t = 0; t < 10; t++) {
        const float* ft = feat2 + (size_t)t * 8 * 64 * 32 * 32;
        const float* hp = t ? outs2 + (size_t)(t-1) * 8 * 96 * 32 * 32 : nullptr;
        float*       ho = outs2 + (size_t)t * 8 * 96 * 32 * 32;
        gru_conv<32,16,1,2,1><<<dim3(1,8,48),128>>>(
            ft,64, hp,96, wd+o_g2, bg2, nullptr, hp, rh, zb, 192);
        gru_conv<32,16,1,2,2><<<dim3(1,8,24),128>>>(
            ft,64, rh,96, wd+o_c2, bc2, zb, hp, ho, nullptr, 96);
    }
    cudaMemcpyAsync(out + 2097152, outs2 + (size_t)9 * 8 * 96 * 32 * 32,
                    (size_t)8 * 96 * 32 * 32 * sizeof(float),
                    cudaMemcpyDeviceToDevice);

    // ======================= Stage 3: 32 -> 16, hid 96 =====================
    conv3x3_k<16,16,32,32,2,16,4,4,4,1,0><<<dim3(1,20,24),256>>>(
        outs2,96, nullptr,0, W3,b3, nullptr,nullptr, feat3,nullptr, 96, 0);

    for (int t = 0; t < 10; t++) {
        const float* ft = feat3 + (size_t)t * 8 * 96 * 16 * 16;
        const float* hp = t ? outs3 + (size_t)(t-1) * 8 * 96 * 16 * 16 : nullptr;
        float*       ho = outs3 + (size_t)t * 8 * 96 * 16 * 16;
        gru_conv<16,8,4,2,1><<<dim3(1,2,48),128>>>(
            ft,96, hp,96, wd+o_g3, bg3, nullptr, hp, rh, zb, 192);
        gru_conv<16,8,4,2,2><<<dim3(1,2,24),128>>>(
            ft,96, rh,96, wd+o_c3, bc3, zb, hp, ho, nullptr, 96);
    }
    cudaMemcpyAsync(out + 2883584, outs3 + (size_t)9 * 8 * 96 * 16 * 16,
                    (size_t)8 * 96 * 16 * 16 * sizeof(float),
                    cudaMemcpyDeviceToDevice);
}